// round 13
// baseline (speedup 1.0000x reference)
#include <cuda_runtime.h>
#include <cuda_fp16.h>
#include <cstdint>

#define MAX_N 50048
#define D 64
#define SLOT_SHIFT 7                      // 128 CSR slots per node (P(deg>=128) ~ 0)

// Scratch (__device__ globals — allocation-free rule; zero-initialized at load)
__device__ int   g_cnt[MAX_N];            // ALWAYS zero at kernel_launch entry (reset by spmm)
__device__ float g_norm[MAX_N];
__device__ __align__(256) uint4 g_h16[(size_t)MAX_N * 8];      // fp16 h rows (128B each)
__device__ int   g_csr[(size_t)MAX_N << SLOT_SHIFT];           // padded CSR, 25.6MB

// ---------------------------------------------------------------------------
// 1) fill2: combined degree-count + CSR placement. 4 edges/thread (int4),
//    4 independent atomic+store chains; padded buckets need no scan.
__global__ void fill_kernel(const int* __restrict__ src,
                            const int* __restrict__ dst, int e) {
    int i = blockIdx.x * blockDim.x + threadIdx.x;
    int base = i * 4;
    if (base + 3 < e) {
        int4 s = *reinterpret_cast<const int4*>(src + base);
        int4 d = *reinterpret_cast<const int4*>(dst + base);
        int p0 = atomicAdd(&g_cnt[d.x], 1);
        int p1 = atomicAdd(&g_cnt[d.y], 1);
        int p2 = atomicAdd(&g_cnt[d.z], 1);
        int p3 = atomicAdd(&g_cnt[d.w], 1);
        g_csr[((size_t)d.x << SLOT_SHIFT) + p0] = s.x;
        g_csr[((size_t)d.y << SLOT_SHIFT) + p1] = s.y;
        g_csr[((size_t)d.z << SLOT_SHIFT) + p2] = s.z;
        g_csr[((size_t)d.w << SLOT_SHIFT) + p3] = s.w;
    } else {
        for (int j = base; j < e; j++) {
            int dd = dst[j];
            int p = atomicAdd(&g_cnt[dd], 1);
            g_csr[((size_t)dd << SLOT_SHIFT) + p] = src[j];
        }
    }
}

// ---------------------------------------------------------------------------
// 2) TF32 tensor-core GEMM — now dependency-free (stores UNNORMALIZED h16).
__device__ __forceinline__ unsigned f2tf32(float f) {
    unsigned u;
    asm("cvt.rna.tf32.f32 %0, %1;" : "=r"(u) : "f"(f));
    return u;
}

__global__ __launch_bounds__(256) void gemm_kernel(const float* __restrict__ x,
                                                   const float* __restrict__ w,
                                                   int n) {
    __shared__ unsigned wt[64][68];   // W transposed [ncol][k], tf32 bits

    int tid  = threadIdx.x;
    int lane = tid & 31;
    int warp = tid >> 5;
    int r0   = blockIdx.x * 128;

#pragma unroll
    for (int s = tid; s < 64 * 16; s += 256) {
        int k = s >> 4, q = s & 15;
        float4 v = *reinterpret_cast<const float4*>(w + k * D + q * 4);
        wt[q * 4 + 0][k] = f2tf32(v.x);
        wt[q * 4 + 1][k] = f2tf32(v.y);
        wt[q * 4 + 2][k] = f2tf32(v.z);
        wt[q * 4 + 3][k] = f2tf32(v.w);
    }
    __syncthreads();

    int grp = lane >> 2;
    int thr = lane & 3;
    int row_lo = r0 + warp * 16 + grp;
    int row_hi = row_lo + 8;
    bool lo_ok = row_lo < n;
    bool hi_ok = row_hi < n;
    const float* xlo = x + (size_t)row_lo * D;
    const float* xhi = x + (size_t)row_hi * D;

    unsigned a[8][4];
#pragma unroll
    for (int kt = 0; kt < 8; kt++) {
        int k0 = kt * 8 + thr;
        a[kt][0] = lo_ok ? f2tf32(__ldg(xlo + k0))     : 0u;
        a[kt][1] = hi_ok ? f2tf32(__ldg(xhi + k0))     : 0u;
        a[kt][2] = lo_ok ? f2tf32(__ldg(xlo + k0 + 4)) : 0u;
        a[kt][3] = hi_ok ? f2tf32(__ldg(xhi + k0 + 4)) : 0u;
    }

    float acc[8][4];
#pragma unroll
    for (int i = 0; i < 8; i++)
#pragma unroll
        for (int j = 0; j < 4; j++) acc[i][j] = 0.f;

#pragma unroll
    for (int kt = 0; kt < 8; kt++) {
        int k0 = kt * 8 + thr;
#pragma unroll
        for (int nt = 0; nt < 8; nt++) {
            unsigned b0 = wt[nt * 8 + grp][k0];
            unsigned b1 = wt[nt * 8 + grp][k0 + 4];
            asm volatile(
                "mma.sync.aligned.m16n8k8.row.col.f32.tf32.tf32.f32 "
                "{%0,%1,%2,%3}, {%4,%5,%6,%7}, {%8,%9}, {%0,%1,%2,%3};"
                : "+f"(acc[nt][0]), "+f"(acc[nt][1]),
                  "+f"(acc[nt][2]), "+f"(acc[nt][3])
                : "r"(a[kt][0]), "r"(a[kt][1]), "r"(a[kt][2]), "r"(a[kt][3]),
                  "r"(b0), "r"(b1));
        }
    }

    unsigned* hb = reinterpret_cast<unsigned*>(g_h16);
#pragma unroll
    for (int nt = 0; nt < 8; nt++) {
        int cslot = nt * 4 + thr;
        if (lo_ok) {
            __half2 h = __floats2half2_rn(acc[nt][0], acc[nt][1]);
            hb[(size_t)row_lo * 32 + cslot] = *reinterpret_cast<unsigned*>(&h);
        }
        if (hi_ok) {
            __half2 h = __floats2half2_rn(acc[nt][2], acc[nt][3]);
            hb[(size_t)row_hi * 32 + cslot] = *reinterpret_cast<unsigned*>(&h);
        }
    }
}

// ---------------------------------------------------------------------------
// 3) normh: h16[row] *= rsqrt(cnt[row]) (fp32 math), writes g_norm.
//    8 threads per row, one uint4 (8 halves) each.
__global__ void normh_kernel(int n) {
    int t = blockIdx.x * blockDim.x + threadIdx.x;
    int row = t >> 3;
    int sub = t & 7;
    if (row >= n) return;
    int c = g_cnt[row];
    float nf = (c > 0) ? rsqrtf((float)c) : 0.0f;
    if (sub == 0) g_norm[row] = nf;

    uint4 v = g_h16[(size_t)row * 8 + sub];
    __half2 h; float2 f;
    *reinterpret_cast<unsigned*>(&h) = v.x; f = __half22float2(h);
    h = __floats2half2_rn(f.x * nf, f.y * nf); v.x = *reinterpret_cast<unsigned*>(&h);
    *reinterpret_cast<unsigned*>(&h) = v.y; f = __half22float2(h);
    h = __floats2half2_rn(f.x * nf, f.y * nf); v.y = *reinterpret_cast<unsigned*>(&h);
    *reinterpret_cast<unsigned*>(&h) = v.z; f = __half22float2(h);
    h = __floats2half2_rn(f.x * nf, f.y * nf); v.z = *reinterpret_cast<unsigned*>(&h);
    *reinterpret_cast<unsigned*>(&h) = v.w; f = __half22float2(h);
    h = __floats2half2_rn(f.x * nf, f.y * nf); v.w = *reinterpret_cast<unsigned*>(&h);
    g_h16[(size_t)row * 8 + sub] = v;
}

// ---------------------------------------------------------------------------
// 4) SpMM + finalize. 8 lanes/node, R11-proven loop (8-edge batches, fresh
//    in-loop csr load, fp16 tree-combine). Padded-CSR addressing; group
//    leader reads cnt then restores the zero invariant.
__device__ __forceinline__ unsigned hadd2u(unsigned a, unsigned b) {
    unsigned r;
    asm("add.rn.f16x2 %0, %1, %2;" : "=r"(r) : "r"(a), "r"(b));
    return r;
}
__device__ __forceinline__ uint4 hadd2v(uint4 a, uint4 b) {
    uint4 r;
    r.x = hadd2u(a.x, b.x); r.y = hadd2u(a.y, b.y);
    r.z = hadd2u(a.z, b.z); r.w = hadd2u(a.w, b.w);
    return r;
}
__device__ __forceinline__ void acc_row(float2* A, uint4 v) {
    __half2 h; float2 f;
    *reinterpret_cast<unsigned*>(&h) = v.x; f = __half22float2(h); A[0].x += f.x; A[0].y += f.y;
    *reinterpret_cast<unsigned*>(&h) = v.y; f = __half22float2(h); A[1].x += f.x; A[1].y += f.y;
    *reinterpret_cast<unsigned*>(&h) = v.z; f = __half22float2(h); A[2].x += f.x; A[2].y += f.y;
    *reinterpret_cast<unsigned*>(&h) = v.w; f = __half22float2(h); A[3].x += f.x; A[3].y += f.y;
}

__global__ __launch_bounds__(256) void spmm_kernel(float* __restrict__ out,
                                                   const float* __restrict__ bias,
                                                   int n) {
    int tid = blockIdx.x * blockDim.x + threadIdx.x;
    int node = tid >> 3;
    if (node >= n) return;
    int lane = threadIdx.x & 31;
    int sub  = lane & 7;
    int gbase = lane & ~7;
    unsigned gmask = 0xffu << gbase;

    int c = 0;
    if (sub == 0) {
        c = g_cnt[node];
        g_cnt[node] = 0;                  // restore zero invariant for next call
    }
    c = __shfl_sync(gmask, c, gbase);
    const int* crow = g_csr + ((size_t)node << SLOT_SHIFT);

    float2 A[4] = {{0.f,0.f},{0.f,0.f},{0.f,0.f},{0.f,0.f}};
    float2 B[4] = {{0.f,0.f},{0.f,0.f},{0.f,0.f},{0.f,0.f}};

    const uint4* hbase = g_h16;
    int j = 0;
    for (; j + 7 < c; j += 8) {
        int my = __ldg(crow + j + sub);
        uint4 v[8];
#pragma unroll
        for (int k = 0; k < 8; k++) {
            int s = __shfl_sync(gmask, my, gbase + k);
            v[k] = __ldg(&hbase[(size_t)s * 8 + sub]);
        }
        uint4 p0 = hadd2v(v[0], v[1]);
        uint4 p1 = hadd2v(v[2], v[3]);
        uint4 p2 = hadd2v(v[4], v[5]);
        uint4 p3 = hadd2v(v[6], v[7]);
        acc_row(A, hadd2v(p0, p1));
        acc_row(B, hadd2v(p2, p3));
    }
    for (; j < c; j++) {
        int s0 = __ldg(crow + j);
        uint4 v0 = __ldg(&hbase[(size_t)s0 * 8 + sub]);
        acc_row(A, v0);
    }

#pragma unroll
    for (int k = 0; k < 4; k++) { A[k].x += B[k].x; A[k].y += B[k].y; }

    float nrm = g_norm[node];
    float4 bv0 = reinterpret_cast<const float4*>(bias)[sub * 2];
    float4 bv1 = reinterpret_cast<const float4*>(bias)[sub * 2 + 1];

    float r[8];
    r[0] = A[0].x * nrm + bv0.x; r[1] = A[0].y * nrm + bv0.y;
    r[2] = A[1].x * nrm + bv0.z; r[3] = A[1].y * nrm + bv0.w;
    r[4] = A[2].x * nrm + bv1.x; r[5] = A[2].y * nrm + bv1.y;
    r[6] = A[3].x * nrm + bv1.z; r[7] = A[3].y * nrm + bv1.w;
#pragma unroll
    for (int k = 0; k < 8; k++)
        r[k] = fmaxf(r[k], 0.f) + log1pf(__expf(-fabsf(r[k])));

    float4* op = reinterpret_cast<float4*>(out + (size_t)node * D + sub * 8);
    op[0] = make_float4(r[0], r[1], r[2], r[3]);
    op[1] = make_float4(r[4], r[5], r[6], r[7]);
}

// ---------------------------------------------------------------------------
// Launch DAG:  { fill2 (stream 0)  ||  gemm (side stream, no deps) }
//              -> normh -> spmm
extern "C" void kernel_launch(void* const* d_in, const int* in_sizes, int n_in,
                              void* d_out, int out_size) {
    // inputs: t, x, weight, bias, src, dst
    const float* x    = (const float*)d_in[1];
    const float* w    = (const float*)d_in[2];
    const float* bias = (const float*)d_in[3];
    const int*   src  = (const int*)d_in[4];
    const int*   dst  = (const int*)d_in[5];
    float*       out  = (float*)d_out;

    int n = in_sizes[1] / D;      // 50000
    int e = in_sizes[4];          // 1,600,000

    int quads = (e + 3) / 4;

    cudaStream_t s2;
    cudaEvent_t ev_fork, ev_join;
    cudaStreamCreateWithFlags(&s2, cudaStreamNonBlocking);
    cudaEventCreateWithFlags(&ev_fork, cudaEventDisableTiming);
    cudaEventCreateWithFlags(&ev_join, cudaEventDisableTiming);

    // fork: gemm on s2 (no dependencies — starts immediately)
    cudaEventRecord(ev_fork, 0);
    cudaStreamWaitEvent(s2, ev_fork, 0);
    gemm_kernel<<<(n + 127) / 128, 256, 0, s2>>>(x, w, n);
    cudaEventRecord(ev_join, s2);

    // trunk: fill2 (counting + placement, padded CSR — no scan needed)
    fill_kernel<<<(quads + 255) / 256, 256>>>(src, dst, e);

    // join: normh needs both fill2 (cnt) and gemm (h16)
    cudaStreamWaitEvent(0, ev_join, 0);
    {
        long long t = (long long)n * 8;
        int blocks = (int)((t + 255) / 256);
        normh_kernel<<<blocks, 256>>>(n);
        spmm_kernel<<<blocks, 256>>>(out, bias, n);
    }
}

// round 14
// speedup vs baseline: 1.1057x; 1.1057x over previous
#include <cuda_runtime.h>
#include <cuda_fp16.h>
#include <cstdint>

#define MAX_N 50048
#define MAX_E 1605632
#define D 64
#define AGG_FLAG 0x40000000

// Scratch (__device__ globals — allocation-free rule; zero-initialized at load)
__device__ int   g_deg[MAX_N];            // ALWAYS zero at kernel_launch entry
__device__ float g_norm[MAX_N];
__device__ __align__(256) uint4 g_h16[(size_t)MAX_N * 8];  // fp16 h rows (128B each)
__device__ int   g_off[MAX_N + 1];
__device__ int   g_cur[MAX_N];
__device__ int   g_csr[MAX_E];
__device__ int   g_state[256];            // scan lookback states (zeroed by deg_kernel)

// ---------------------------------------------------------------------------
// 1) count in-degree (int4-vectorized); also zero scan states for this call
__global__ void deg_kernel(const int* __restrict__ dst, int e) {
    int i = blockIdx.x * blockDim.x + threadIdx.x;
    if (i < 256) g_state[i] = 0;
    int base = i * 4;
    if (base + 3 < e) {
        int4 d = *reinterpret_cast<const int4*>(dst + base);
        atomicAdd(&g_deg[d.x], 1);
        atomicAdd(&g_deg[d.y], 1);
        atomicAdd(&g_deg[d.z], 1);
        atomicAdd(&g_deg[d.w], 1);
    } else {
        for (int j = base; j < e; j++) atomicAdd(&g_deg[dst[j]], 1);
    }
}

// ---------------------------------------------------------------------------
__device__ __forceinline__ int warp_incl_scan(int v, int lane) {
#pragma unroll
    for (int o = 1; o < 32; o <<= 1) {
        int t = __shfl_up_sync(0xffffffffu, v, o);
        if (lane >= o) v += t;
    }
    return v;
}

// 2) Single-pass fused scan (non-chained aggregate lookback).
//    Poll uses atomicAdd(p, 0) — the known-good form.
__global__ void scan_kernel(int n, int e) {
    __shared__ int wsum[8];
    __shared__ int bprefix;
    int tid  = threadIdx.x;
    int lane = tid & 31;
    int wid  = tid >> 5;
    int b    = blockIdx.x;
    int i    = b * 256 + tid;

    int v = (i < n) ? g_deg[i] : 0;

    int incl = warp_incl_scan(v, lane);
    if (lane == 31) wsum[wid] = incl;
    __syncthreads();
    if (wid == 0) {
        int wv = (lane < 8) ? wsum[lane] : 0;
        wv = warp_incl_scan(wv, lane);
        if (lane < 8) wsum[lane] = wv;
    }
    __syncthreads();
    int base = (wid > 0) ? wsum[wid - 1] : 0;
    int excl = base + incl - v;

    if (tid == 255) atomicExch(&g_state[b], (base + incl) | AGG_FLAG);

    if (wid == 0) {
        int sum = 0;
        for (int p0 = 0; p0 < b; p0 += 32) {
            int p = p0 + lane;
            int s = 0;
            if (p < b) {
                do { s = atomicAdd(&g_state[p], 0); } while ((s & AGG_FLAG) == 0);
                s &= ~AGG_FLAG;
            }
#pragma unroll
            for (int o = 16; o; o >>= 1) s += __shfl_down_sync(0xffffffffu, s, o);
            if (lane == 0) sum += s;
        }
        if (lane == 0) bprefix = sum;
    }
    __syncthreads();

    if (i < n) {
        int o = bprefix + excl;
        g_off[i]  = o;
        g_cur[i]  = o;
        g_norm[i] = v > 0 ? rsqrtf((float)v) : 0.0f;
        g_deg[i]  = 0;                 // restore invariant for next call
    }
    if (i == 0) g_off[n] = e;
}

// ---------------------------------------------------------------------------
// 3) Fill CSR (int4-vectorized, 4 edges/thread — the R11 known-good config)
__global__ void fill_kernel(const int* __restrict__ src,
                            const int* __restrict__ dst, int e) {
    int i = blockIdx.x * blockDim.x + threadIdx.x;
    int base = i * 4;
    if (base + 3 < e) {
        int4 s = *reinterpret_cast<const int4*>(src + base);
        int4 d = *reinterpret_cast<const int4*>(dst + base);
        g_csr[atomicAdd(&g_cur[d.x], 1)] = s.x;
        g_csr[atomicAdd(&g_cur[d.y], 1)] = s.y;
        g_csr[atomicAdd(&g_cur[d.z], 1)] = s.z;
        g_csr[atomicAdd(&g_cur[d.w], 1)] = s.w;
    } else {
        for (int j = base; j < e; j++)
            g_csr[atomicAdd(&g_cur[dst[j]], 1)] = src[j];
    }
}

// ---------------------------------------------------------------------------
// 4) TF32 tensor-core GEMM (128 rows/block, prefetched A frags). Unchanged.
__device__ __forceinline__ unsigned f2tf32(float f) {
    unsigned u;
    asm("cvt.rna.tf32.f32 %0, %1;" : "=r"(u) : "f"(f));
    return u;
}

__global__ __launch_bounds__(256) void gemm_kernel(const float* __restrict__ x,
                                                   const float* __restrict__ w,
                                                   int n) {
    __shared__ unsigned wt[64][68];   // W transposed [ncol][k], tf32 bits

    int tid  = threadIdx.x;
    int lane = tid & 31;
    int warp = tid >> 5;
    int r0   = blockIdx.x * 128;

#pragma unroll
    for (int s = tid; s < 64 * 16; s += 256) {
        int k = s >> 4, q = s & 15;
        float4 v = *reinterpret_cast<const float4*>(w + k * D + q * 4);
        wt[q * 4 + 0][k] = f2tf32(v.x);
        wt[q * 4 + 1][k] = f2tf32(v.y);
        wt[q * 4 + 2][k] = f2tf32(v.z);
        wt[q * 4 + 3][k] = f2tf32(v.w);
    }
    __syncthreads();

    int grp = lane >> 2;
    int thr = lane & 3;
    int row_lo = r0 + warp * 16 + grp;
    int row_hi = row_lo + 8;
    bool lo_ok = row_lo < n;
    bool hi_ok = row_hi < n;
    const float* xlo = x + (size_t)row_lo * D;
    const float* xhi = x + (size_t)row_hi * D;

    unsigned a[8][4];
#pragma unroll
    for (int kt = 0; kt < 8; kt++) {
        int k0 = kt * 8 + thr;
        a[kt][0] = lo_ok ? f2tf32(__ldg(xlo + k0))     : 0u;
        a[kt][1] = hi_ok ? f2tf32(__ldg(xhi + k0))     : 0u;
        a[kt][2] = lo_ok ? f2tf32(__ldg(xlo + k0 + 4)) : 0u;
        a[kt][3] = hi_ok ? f2tf32(__ldg(xhi + k0 + 4)) : 0u;
    }

    float acc[8][4];
#pragma unroll
    for (int i = 0; i < 8; i++)
#pragma unroll
        for (int j = 0; j < 4; j++) acc[i][j] = 0.f;

#pragma unroll
    for (int kt = 0; kt < 8; kt++) {
        int k0 = kt * 8 + thr;
#pragma unroll
        for (int nt = 0; nt < 8; nt++) {
            unsigned b0 = wt[nt * 8 + grp][k0];
            unsigned b1 = wt[nt * 8 + grp][k0 + 4];
            asm volatile(
                "mma.sync.aligned.m16n8k8.row.col.f32.tf32.tf32.f32 "
                "{%0,%1,%2,%3}, {%4,%5,%6,%7}, {%8,%9}, {%0,%1,%2,%3};"
                : "+f"(acc[nt][0]), "+f"(acc[nt][1]),
                  "+f"(acc[nt][2]), "+f"(acc[nt][3])
                : "r"(a[kt][0]), "r"(a[kt][1]), "r"(a[kt][2]), "r"(a[kt][3]),
                  "r"(b0), "r"(b1));
        }
    }

    float n_lo = lo_ok ? g_norm[row_lo] : 0.f;
    float n_hi = hi_ok ? g_norm[row_hi] : 0.f;
    unsigned* hb = reinterpret_cast<unsigned*>(g_h16);
#pragma unroll
    for (int nt = 0; nt < 8; nt++) {
        int cslot = nt * 4 + thr;
        if (lo_ok) {
            __half2 h = __floats2half2_rn(acc[nt][0] * n_lo, acc[nt][1] * n_lo);
            hb[(size_t)row_lo * 32 + cslot] = *reinterpret_cast<unsigned*>(&h);
        }
        if (hi_ok) {
            __half2 h = __floats2half2_rn(acc[nt][2] * n_hi, acc[nt][3] * n_hi);
            hb[(size_t)row_hi * 32 + cslot] = *reinterpret_cast<unsigned*>(&h);
        }
    }
}

// ---------------------------------------------------------------------------
// 5) SpMM + finalize. NOW 16 lanes/node (uint2 = 8B per lane per edge):
//    halves per-thread live state (~45 regs -> ~5 blocks/SM, occ ~62%).
//    16-edge batches, fresh in-loop csr load, fp16 tree 8->4->2 per half.
__device__ __forceinline__ unsigned hadd2u(unsigned a, unsigned b) {
    unsigned r;
    asm("add.rn.f16x2 %0, %1, %2;" : "=r"(r) : "r"(a), "r"(b));
    return r;
}
__device__ __forceinline__ uint2 hadd2v2(uint2 a, uint2 b) {
    uint2 r;
    r.x = hadd2u(a.x, b.x);
    r.y = hadd2u(a.y, b.y);
    return r;
}
__device__ __forceinline__ void acc_row2(float2* A, uint2 v) {
    __half2 h; float2 f;
    *reinterpret_cast<unsigned*>(&h) = v.x; f = __half22float2(h); A[0].x += f.x; A[0].y += f.y;
    *reinterpret_cast<unsigned*>(&h) = v.y; f = __half22float2(h); A[1].x += f.x; A[1].y += f.y;
}

__global__ __launch_bounds__(256) void spmm_kernel(float* __restrict__ out,
                                                   const float* __restrict__ bias,
                                                   int n) {
    int tid = blockIdx.x * blockDim.x + threadIdx.x;
    int node = tid >> 4;
    if (node >= n) return;
    int lane = threadIdx.x & 31;
    int sub  = lane & 15;
    int gbase = lane & ~15;                  // 0 or 16
    unsigned gmask = 0xffffu << gbase;

    int beg = g_off[node];
    int end = g_off[node + 1];

    float2 A[2] = {{0.f,0.f},{0.f,0.f}};
    float2 B[2] = {{0.f,0.f},{0.f,0.f}};

    const uint2* hbase = reinterpret_cast<const uint2*>(g_h16);  // 16 uint2 per row
    int e = beg;
    // full 16-edge batches (unguarded)
    for (; e + 15 < end; e += 16) {
        int my = __ldg(&g_csr[e + sub]);     // 16 coalesced indices per group
#pragma unroll
        for (int w = 0; w < 2; w++) {        // two 8-edge waves
            uint2 v[8];
#pragma unroll
            for (int j = 0; j < 8; j++) {
                int s = __shfl_sync(gmask, my, gbase + w * 8 + j);
                v[j] = __ldg(&hbase[(size_t)s * 16 + sub]);
            }
            uint2 p0 = hadd2v2(v[0], v[1]);
            uint2 p1 = hadd2v2(v[2], v[3]);
            uint2 p2 = hadd2v2(v[4], v[5]);
            uint2 p3 = hadd2v2(v[6], v[7]);
            acc_row2(A, hadd2v2(p0, p1));
            acc_row2(B, hadd2v2(p2, p3));
        }
    }
    // tail: one guarded 16-batch (clamped index load, zero-padded tree)
    if (e < end) {
        int rem = end - e;                    // 1..15
        int idx = e + sub; if (idx >= end) idx = end - 1;
        int my = __ldg(&g_csr[idx]);
#pragma unroll
        for (int w = 0; w < 2; w++) {
            uint2 v[8];
#pragma unroll
            for (int j = 0; j < 8; j++) {
                int jj = w * 8 + j;
                int s = __shfl_sync(gmask, my, gbase + jj);
                v[j] = (jj < rem) ? __ldg(&hbase[(size_t)s * 16 + sub])
                                  : make_uint2(0u, 0u);
            }
            uint2 p0 = hadd2v2(v[0], v[1]);
            uint2 p1 = hadd2v2(v[2], v[3]);
            uint2 p2 = hadd2v2(v[4], v[5]);
            uint2 p3 = hadd2v2(v[6], v[7]);
            acc_row2(A, hadd2v2(p0, p1));
            acc_row2(B, hadd2v2(p2, p3));
        }
    }

    A[0].x += B[0].x; A[0].y += B[0].y;
    A[1].x += B[1].x; A[1].y += B[1].y;

    float nrm = g_norm[node];
    float4 bv = reinterpret_cast<const float4*>(bias)[sub];

    float r[4];
    r[0] = A[0].x * nrm + bv.x;
    r[1] = A[0].y * nrm + bv.y;
    r[2] = A[1].x * nrm + bv.z;
    r[3] = A[1].y * nrm + bv.w;
#pragma unroll
    for (int k = 0; k < 4; k++)
        r[k] = fmaxf(r[k], 0.f) + log1pf(__expf(-fabsf(r[k])));

    *reinterpret_cast<float4*>(out + (size_t)node * D + sub * 4) =
        make_float4(r[0], r[1], r[2], r[3]);
}

// ---------------------------------------------------------------------------
// Launch DAG:  deg -> scan -> { fill (stream 0)  ||  gemm (side stream) } -> spmm
extern "C" void kernel_launch(void* const* d_in, const int* in_sizes, int n_in,
                              void* d_out, int out_size) {
    // inputs: t, x, weight, bias, src, dst
    const float* x    = (const float*)d_in[1];
    const float* w    = (const float*)d_in[2];
    const float* bias = (const float*)d_in[3];
    const int*   src  = (const int*)d_in[4];
    const int*   dst  = (const int*)d_in[5];
    float*       out  = (float*)d_out;

    int n = in_sizes[1] / D;      // 50000
    int e = in_sizes[4];          // 1,600,000

    int nblocks256 = (n + 255) / 256;   // 196
    int quads = (e + 3) / 4;

    cudaStream_t s2;
    cudaEvent_t ev_fork, ev_join;
    cudaStreamCreateWithFlags(&s2, cudaStreamNonBlocking);
    cudaEventCreateWithFlags(&ev_fork, cudaEventDisableTiming);
    cudaEventCreateWithFlags(&ev_join, cudaEventDisableTiming);

    // trunk: deg -> scan
    deg_kernel<<<(quads + 255) / 256, 256>>>(dst, e);
    scan_kernel<<<nblocks256, 256>>>(n, e);

    // fork: gemm on s2 (needs g_norm from scan), concurrent with fill
    cudaEventRecord(ev_fork, 0);
    cudaStreamWaitEvent(s2, ev_fork, 0);
    gemm_kernel<<<(n + 127) / 128, 256, 0, s2>>>(x, w, n);
    cudaEventRecord(ev_join, s2);

    // trunk: fill (independent of gemm)
    fill_kernel<<<(quads + 255) / 256, 256>>>(src, dst, e);

    // join: spmm needs both fill (stream 0 order) and gemm (event)
    cudaStreamWaitEvent(0, ev_join, 0);
    {
        long long threads = (long long)n * 16;
        int blocks = (int)((threads + 255) / 256);
        spmm_kernel<<<blocks, 256>>>(out, bias, n);
    }
}

// round 15
// speedup vs baseline: 1.2026x; 1.0876x over previous
#include <cuda_runtime.h>
#include <cuda_fp16.h>
#include <cstdint>

#define MAX_N 50048
#define MAX_E 1605632
#define D 64
#define AGG_FLAG 0x40000000

// Scratch (__device__ globals — allocation-free rule; zero-initialized at load)
__device__ int   g_deg[MAX_N];            // ALWAYS zero at kernel_launch entry
__device__ float g_norm[MAX_N];
__device__ __align__(256) uint4 g_h16[(size_t)MAX_N * 8];  // fp16 h rows (128B each)
__device__ int   g_off[MAX_N + 1];
__device__ int   g_csr[MAX_E];
__device__ int   g_rank[MAX_E];           // per-edge rank within its dst bucket
__device__ int   g_state[256];            // scan lookback states (zeroed by deg_kernel)

// ---------------------------------------------------------------------------
// 1) count in-degree AND capture each edge's rank (the atomic's return value,
//    previously discarded). Coalesced int4 rank store. Also zero scan states.
__global__ void deg_kernel(const int* __restrict__ dst, int e) {
    int i = blockIdx.x * blockDim.x + threadIdx.x;
    if (i < 256) g_state[i] = 0;
    int base = i * 4;
    if (base + 3 < e) {
        int4 d = *reinterpret_cast<const int4*>(dst + base);
        int4 r;
        r.x = atomicAdd(&g_deg[d.x], 1);
        r.y = atomicAdd(&g_deg[d.y], 1);
        r.z = atomicAdd(&g_deg[d.z], 1);
        r.w = atomicAdd(&g_deg[d.w], 1);
        *reinterpret_cast<int4*>(g_rank + base) = r;
    } else {
        for (int j = base; j < e; j++)
            g_rank[j] = atomicAdd(&g_deg[dst[j]], 1);
    }
}

// ---------------------------------------------------------------------------
__device__ __forceinline__ int warp_incl_scan(int v, int lane) {
#pragma unroll
    for (int o = 1; o < 32; o <<= 1) {
        int t = __shfl_up_sync(0xffffffffu, v, o);
        if (lane >= o) v += t;
    }
    return v;
}

// 2) Single-pass fused scan (non-chained aggregate lookback).
//    Poll uses atomicAdd(p, 0) — the known-good form.
__global__ void scan_kernel(int n, int e) {
    __shared__ int wsum[8];
    __shared__ int bprefix;
    int tid  = threadIdx.x;
    int lane = tid & 31;
    int wid  = tid >> 5;
    int b    = blockIdx.x;
    int i    = b * 256 + tid;

    int v = (i < n) ? g_deg[i] : 0;

    int incl = warp_incl_scan(v, lane);
    if (lane == 31) wsum[wid] = incl;
    __syncthreads();
    if (wid == 0) {
        int wv = (lane < 8) ? wsum[lane] : 0;
        wv = warp_incl_scan(wv, lane);
        if (lane < 8) wsum[lane] = wv;
    }
    __syncthreads();
    int base = (wid > 0) ? wsum[wid - 1] : 0;
    int excl = base + incl - v;

    if (tid == 255) atomicExch(&g_state[b], (base + incl) | AGG_FLAG);

    if (wid == 0) {
        int sum = 0;
        for (int p0 = 0; p0 < b; p0 += 32) {
            int p = p0 + lane;
            int s = 0;
            if (p < b) {
                do { s = atomicAdd(&g_state[p], 0); } while ((s & AGG_FLAG) == 0);
                s &= ~AGG_FLAG;
            }
#pragma unroll
            for (int o = 16; o; o >>= 1) s += __shfl_down_sync(0xffffffffu, s, o);
            if (lane == 0) sum += s;
        }
        if (lane == 0) bprefix = sum;
    }
    __syncthreads();

    if (i < n) {
        int o = bprefix + excl;
        g_off[i]  = o;
        g_norm[i] = v > 0 ? rsqrtf((float)v) : 0.0f;
        g_deg[i]  = 0;                 // restore invariant for next call
    }
    if (i == 0) g_off[n] = e;
}

// ---------------------------------------------------------------------------
// 3) Fill CSR — ATOMIC-FREE: pos = off[dst] + rank. Per edge: coalesced
//    src/dst/rank loads + one random L2 read + scattered store; 4 independent
//    chains per thread, no atomic-return serialization.
__global__ void fill_kernel(const int* __restrict__ src,
                            const int* __restrict__ dst, int e) {
    int i = blockIdx.x * blockDim.x + threadIdx.x;
    int base = i * 4;
    if (base + 3 < e) {
        int4 s = *reinterpret_cast<const int4*>(src + base);
        int4 d = *reinterpret_cast<const int4*>(dst + base);
        int4 r = *reinterpret_cast<const int4*>(g_rank + base);
        int o0 = __ldg(&g_off[d.x]);
        int o1 = __ldg(&g_off[d.y]);
        int o2 = __ldg(&g_off[d.z]);
        int o3 = __ldg(&g_off[d.w]);
        g_csr[o0 + r.x] = s.x;
        g_csr[o1 + r.y] = s.y;
        g_csr[o2 + r.z] = s.z;
        g_csr[o3 + r.w] = s.w;
    } else {
        for (int j = base; j < e; j++)
            g_csr[__ldg(&g_off[dst[j]]) + g_rank[j]] = src[j];
    }
}

// ---------------------------------------------------------------------------
// 4) TF32 tensor-core GEMM (128 rows/block, prefetched A frags). Unchanged.
__device__ __forceinline__ unsigned f2tf32(float f) {
    unsigned u;
    asm("cvt.rna.tf32.f32 %0, %1;" : "=r"(u) : "f"(f));
    return u;
}

__global__ __launch_bounds__(256) void gemm_kernel(const float* __restrict__ x,
                                                   const float* __restrict__ w,
                                                   int n) {
    __shared__ unsigned wt[64][68];   // W transposed [ncol][k], tf32 bits

    int tid  = threadIdx.x;
    int lane = tid & 31;
    int warp = tid >> 5;
    int r0   = blockIdx.x * 128;

#pragma unroll
    for (int s = tid; s < 64 * 16; s += 256) {
        int k = s >> 4, q = s & 15;
        float4 v = *reinterpret_cast<const float4*>(w + k * D + q * 4);
        wt[q * 4 + 0][k] = f2tf32(v.x);
        wt[q * 4 + 1][k] = f2tf32(v.y);
        wt[q * 4 + 2][k] = f2tf32(v.z);
        wt[q * 4 + 3][k] = f2tf32(v.w);
    }
    __syncthreads();

    int grp = lane >> 2;
    int thr = lane & 3;
    int row_lo = r0 + warp * 16 + grp;
    int row_hi = row_lo + 8;
    bool lo_ok = row_lo < n;
    bool hi_ok = row_hi < n;
    const float* xlo = x + (size_t)row_lo * D;
    const float* xhi = x + (size_t)row_hi * D;

    unsigned a[8][4];
#pragma unroll
    for (int kt = 0; kt < 8; kt++) {
        int k0 = kt * 8 + thr;
        a[kt][0] = lo_ok ? f2tf32(__ldg(xlo + k0))     : 0u;
        a[kt][1] = hi_ok ? f2tf32(__ldg(xhi + k0))     : 0u;
        a[kt][2] = lo_ok ? f2tf32(__ldg(xlo + k0 + 4)) : 0u;
        a[kt][3] = hi_ok ? f2tf32(__ldg(xhi + k0 + 4)) : 0u;
    }

    float acc[8][4];
#pragma unroll
    for (int i = 0; i < 8; i++)
#pragma unroll
        for (int j = 0; j < 4; j++) acc[i][j] = 0.f;

#pragma unroll
    for (int kt = 0; kt < 8; kt++) {
        int k0 = kt * 8 + thr;
#pragma unroll
        for (int nt = 0; nt < 8; nt++) {
            unsigned b0 = wt[nt * 8 + grp][k0];
            unsigned b1 = wt[nt * 8 + grp][k0 + 4];
            asm volatile(
                "mma.sync.aligned.m16n8k8.row.col.f32.tf32.tf32.f32 "
                "{%0,%1,%2,%3}, {%4,%5,%6,%7}, {%8,%9}, {%0,%1,%2,%3};"
                : "+f"(acc[nt][0]), "+f"(acc[nt][1]),
                  "+f"(acc[nt][2]), "+f"(acc[nt][3])
                : "r"(a[kt][0]), "r"(a[kt][1]), "r"(a[kt][2]), "r"(a[kt][3]),
                  "r"(b0), "r"(b1));
        }
    }

    float n_lo = lo_ok ? g_norm[row_lo] : 0.f;
    float n_hi = hi_ok ? g_norm[row_hi] : 0.f;
    unsigned* hb = reinterpret_cast<unsigned*>(g_h16);
#pragma unroll
    for (int nt = 0; nt < 8; nt++) {
        int cslot = nt * 4 + thr;
        if (lo_ok) {
            __half2 h = __floats2half2_rn(acc[nt][0] * n_lo, acc[nt][1] * n_lo);
            hb[(size_t)row_lo * 32 + cslot] = *reinterpret_cast<unsigned*>(&h);
        }
        if (hi_ok) {
            __half2 h = __floats2half2_rn(acc[nt][2] * n_hi, acc[nt][3] * n_hi);
            hb[(size_t)row_hi * 32 + cslot] = *reinterpret_cast<unsigned*>(&h);
        }
    }
}

// ---------------------------------------------------------------------------
// 5) SpMM + finalize — R11 proven shape: 8 lanes/node, uint4 gathers,
//    8-edge batches, fresh in-loop csr load, fp16 tree-combine 8->4->2.
__device__ __forceinline__ unsigned hadd2u(unsigned a, unsigned b) {
    unsigned r;
    asm("add.rn.f16x2 %0, %1, %2;" : "=r"(r) : "r"(a), "r"(b));
    return r;
}
__device__ __forceinline__ uint4 hadd2v(uint4 a, uint4 b) {
    uint4 r;
    r.x = hadd2u(a.x, b.x); r.y = hadd2u(a.y, b.y);
    r.z = hadd2u(a.z, b.z); r.w = hadd2u(a.w, b.w);
    return r;
}
__device__ __forceinline__ void acc_row(float2* A, uint4 v) {
    __half2 h; float2 f;
    *reinterpret_cast<unsigned*>(&h) = v.x; f = __half22float2(h); A[0].x += f.x; A[0].y += f.y;
    *reinterpret_cast<unsigned*>(&h) = v.y; f = __half22float2(h); A[1].x += f.x; A[1].y += f.y;
    *reinterpret_cast<unsigned*>(&h) = v.z; f = __half22float2(h); A[2].x += f.x; A[2].y += f.y;
    *reinterpret_cast<unsigned*>(&h) = v.w; f = __half22float2(h); A[3].x += f.x; A[3].y += f.y;
}

__global__ __launch_bounds__(256) void spmm_kernel(float* __restrict__ out,
                                                   const float* __restrict__ bias,
                                                   int n) {
    int tid = blockIdx.x * blockDim.x + threadIdx.x;
    int node = tid >> 3;
    if (node >= n) return;
    int lane = threadIdx.x & 31;
    int sub  = lane & 7;
    int gbase = lane & ~7;
    unsigned gmask = 0xffu << gbase;

    int beg = g_off[node];
    int end = g_off[node + 1];

    float2 A[4] = {{0.f,0.f},{0.f,0.f},{0.f,0.f},{0.f,0.f}};
    float2 B[4] = {{0.f,0.f},{0.f,0.f},{0.f,0.f},{0.f,0.f}};

    const uint4* hbase = g_h16;
    int e = beg;
    for (; e + 7 < end; e += 8) {
        int my = __ldg(&g_csr[e + sub]);
        uint4 v[8];
#pragma unroll
        for (int j = 0; j < 8; j++) {
            int s = __shfl_sync(gmask, my, gbase + j);
            v[j] = __ldg(&hbase[(size_t)s * 8 + sub]);
        }
        uint4 p0 = hadd2v(v[0], v[1]);
        uint4 p1 = hadd2v(v[2], v[3]);
        uint4 p2 = hadd2v(v[4], v[5]);
        uint4 p3 = hadd2v(v[6], v[7]);
        acc_row(A, hadd2v(p0, p1));
        acc_row(B, hadd2v(p2, p3));
    }
    for (; e < end; e++) {
        int s0 = __ldg(&g_csr[e]);
        uint4 v0 = __ldg(&hbase[(size_t)s0 * 8 + sub]);
        acc_row(A, v0);
    }

#pragma unroll
    for (int j = 0; j < 4; j++) { A[j].x += B[j].x; A[j].y += B[j].y; }

    float nrm = g_norm[node];
    float4 bv0 = reinterpret_cast<const float4*>(bias)[sub * 2];
    float4 bv1 = reinterpret_cast<const float4*>(bias)[sub * 2 + 1];

    float r[8];
    r[0] = A[0].x * nrm + bv0.x; r[1] = A[0].y * nrm + bv0.y;
    r[2] = A[1].x * nrm + bv0.z; r[3] = A[1].y * nrm + bv0.w;
    r[4] = A[2].x * nrm + bv1.x; r[5] = A[2].y * nrm + bv1.y;
    r[6] = A[3].x * nrm + bv1.z; r[7] = A[3].y * nrm + bv1.w;
#pragma unroll
    for (int j = 0; j < 8; j++)
        r[j] = fmaxf(r[j], 0.f) + log1pf(__expf(-fabsf(r[j])));

    float4* op = reinterpret_cast<float4*>(out + (size_t)node * D + sub * 8);
    op[0] = make_float4(r[0], r[1], r[2], r[3]);
    op[1] = make_float4(r[4], r[5], r[6], r[7]);
}

// ---------------------------------------------------------------------------
// Launch DAG:  deg -> scan -> { fill (stream 0)  ||  gemm (side stream) } -> spmm
extern "C" void kernel_launch(void* const* d_in, const int* in_sizes, int n_in,
                              void* d_out, int out_size) {
    // inputs: t, x, weight, bias, src, dst
    const float* x    = (const float*)d_in[1];
    const float* w    = (const float*)d_in[2];
    const float* bias = (const float*)d_in[3];
    const int*   src  = (const int*)d_in[4];
    const int*   dst  = (const int*)d_in[5];
    float*       out  = (float*)d_out;

    int n = in_sizes[1] / D;      // 50000
    int e = in_sizes[4];          // 1,600,000

    int nblocks256 = (n + 255) / 256;   // 196
    int quads = (e + 3) / 4;

    cudaStream_t s2;
    cudaEvent_t ev_fork, ev_join;
    cudaStreamCreateWithFlags(&s2, cudaStreamNonBlocking);
    cudaEventCreateWithFlags(&ev_fork, cudaEventDisableTiming);
    cudaEventCreateWithFlags(&ev_join, cudaEventDisableTiming);

    // trunk: deg (counts + ranks) -> scan (offsets + norm)
    deg_kernel<<<(quads + 255) / 256, 256>>>(dst, e);
    scan_kernel<<<nblocks256, 256>>>(n, e);

    // fork: gemm on s2 (needs g_norm from scan), concurrent with fill
    cudaEventRecord(ev_fork, 0);
    cudaStreamWaitEvent(s2, ev_fork, 0);
    gemm_kernel<<<(n + 127) / 128, 256, 0, s2>>>(x, w, n);
    cudaEventRecord(ev_join, s2);

    // trunk: fill (atomic-free: off[dst] + rank)
    fill_kernel<<<(quads + 255) / 256, 256>>>(src, dst, e);

    // join: spmm needs both fill (stream 0 order) and gemm (event)
    cudaStreamWaitEvent(0, ev_join, 0);
    {
        long long threads = (long long)n * 8;
        int blocks = (int)((threads + 255) / 256);
        spmm_kernel<<<blocks, 256>>>(out, bias, n);
    }
}